// round 15
// baseline (speedup 1.0000x reference)
#include <cuda_runtime.h>
#include <cuda.h>
#include <cuda_fp16.h>
#include <cstdint>
#include <math.h>

#define BATCH 16384
#define OUTC  523   // 7 + 4 + 512

// ========================= PTX helpers =========================
__device__ __forceinline__ uint32_t smem_u32(const void* p) {
    uint32_t a;
    asm("{ .reg .u64 t; cvta.to.shared.u64 t, %1; cvt.u32.u64 %0, t; }" : "=r"(a) : "l"(p));
    return a;
}
__device__ __forceinline__ void ldmx4(uint32_t& r0, uint32_t& r1, uint32_t& r2, uint32_t& r3, uint32_t addr) {
    asm volatile("ldmatrix.sync.aligned.m8n8.x4.shared.b16 {%0,%1,%2,%3}, [%4];"
                 : "=r"(r0), "=r"(r1), "=r"(r2), "=r"(r3) : "r"(addr));
}
__device__ __forceinline__ void mma16816(float* c, const uint32_t* a, uint32_t b0, uint32_t b1) {
    asm volatile("mma.sync.aligned.m16n8k16.row.col.f32.f16.f16.f32 "
                 "{%0,%1,%2,%3}, {%4,%5,%6,%7}, {%8,%9}, {%0,%1,%2,%3};"
                 : "+f"(c[0]), "+f"(c[1]), "+f"(c[2]), "+f"(c[3])
                 : "r"(a[0]), "r"(a[1]), "r"(a[2]), "r"(a[3]), "r"(b0), "r"(b1));
}
__device__ __forceinline__ uint32_t swz128(uint32_t off) { return off ^ ((off >> 3) & 0x70); }

__device__ __forceinline__ void tma2d(uint32_t dst, const CUtensorMap* map, int cx, int cy, uint32_t mbar) {
    asm volatile("cp.async.bulk.tensor.2d.shared::cta.global.tile.mbarrier::complete_tx::bytes "
                 "[%0], [%1, {%2, %3}], [%4];"
                 :: "r"(dst), "l"(map), "r"(cx), "r"(cy), "r"(mbar) : "memory");
}
#define MBARRIER_INIT(addr, cnt) \
    asm volatile("mbarrier.init.shared.b64 [%0], %1;" :: "r"((uint32_t)(addr)), "r"((uint32_t)(cnt)) : "memory")
#define MBARRIER_ARRIVE(addr) \
    asm volatile("mbarrier.arrive.shared.b64 _, [%0];" :: "r"((uint32_t)(addr)) : "memory")
#define MBARRIER_EXPECT_TX(addr, bytes) \
    asm volatile("mbarrier.arrive.expect_tx.shared.b64 _, [%0], %1;" \
        :: "r"((uint32_t)(addr)), "r"((uint32_t)(bytes)) : "memory")
#define MBARRIER_WAIT_PARITY(mbar_smem_addr, phase_parity) do { \
    uint32_t _mbar = (uint32_t)(mbar_smem_addr); \
    uint32_t _parity = (uint32_t)(phase_parity); \
    uint32_t _done; \
    asm volatile("{\n\t.reg .pred p;\n\t" \
        "mbarrier.try_wait.parity.acquire.cta.shared::cta.b64 p, [%1], %2;\n\t" \
        "selp.b32 %0, 1, 0, p;\n\t}" : "=r"(_done) : "r"(_mbar), "r"(_parity) : "memory"); \
    if (!_done) { \
        asm volatile("{\n\t.reg .pred P1;\n\t" \
            "WAIT_LOOP_%=:\n\t" \
            "mbarrier.try_wait.parity.acquire.cta.shared::cta.b64 P1, [%0], %1, 0x989680;\n\t" \
            "@P1 bra.uni WAIT_DONE_%=;\n\t" \
            "bra.uni WAIT_LOOP_%=;\n\t" \
            "WAIT_DONE_%=:\n\t}" :: "r"(_mbar), "r"(_parity) : "memory"); \
    } \
} while(0)

// ========================= scratch =========================
__device__ __align__(1024) __half g_x[BATCH * 1024];
__device__ __align__(1024) __half g_y1[BATCH * 1024];
__device__ __align__(1024) __half g_d1[BATCH * 1024];
__device__ __align__(1024) __half g_z1[BATCH * 1024];   // bucket order
__device__ __align__(1024) __half g_z2[BATCH * 1024];   // bucket order
__device__ __align__(1024) __half g_t1[BATCH * 256];
__device__ float g_fy[BATCH * 1024];
__device__ float g_fd[BATCH * 1024];
__device__ float g_ft[BATCH * 256];
__device__ __align__(1024) __half g_wh[10300000];       // single-fp16 weight pool
__device__ int g_ridx[BATCH];
__device__ int g_pos[BATCH];
__device__ int g_cnt[8];
__device__ int g_off[8];

// weight-pool offsets (elements)
#define OFF_TW1 0             // [256,256]
#define OFF_L1  65536         // [3328,1024]: yw0|dw0|zw0'|tw0
#define OFF_YW1 3473408
#define OFF_DW1 4521984
#define OFF_ZW1 5570560
#define OFF_ZHW 6619136       // [3584,1024]

__device__ __forceinline__ float elu_f(float v) { return v > 0.f ? v : expm1f(v); }
__device__ __forceinline__ float softplus_f(float v) {
    return fmaxf(v, 0.f) + log1pf(expf(-fabsf(v)));
}

// ========================= fused bucketing =========================
__global__ void bucket_all(const int* __restrict__ t) {
    __shared__ int scnt[8];
    __shared__ int scur[8];
    int tid = threadIdx.x;
    if (tid < 8) scnt[tid] = 0;
    __syncthreads();
    for (int i = tid; i < BATCH; i += 1024) atomicAdd(&scnt[t[i]], 1);
    __syncthreads();
    if (tid == 0) {
        int s = 0;
        for (int k = 0; k < 7; k++) { g_cnt[k] = scnt[k]; g_off[k] = s; scur[k] = s; s += scnt[k]; }
    }
    __syncthreads();
    for (int i = tid; i < BATCH; i += 1024) {
        int p = atomicAdd(&scur[t[i]], 1);
        g_ridx[p] = i;
        g_pos[i] = p;
    }
}

// ========================= preprocessing =========================
__global__ void xconv_kernel(const float* __restrict__ x, __half* __restrict__ o, int n) {
    int i = (blockIdx.x * blockDim.x + threadIdx.x) * 2;
    if (i < n) {
        float2 v = *(const float2*)(x + i);
        __half2 h; h.x = __float2half(v.x); h.y = __float2half(v.y);
        *(__half2*)(o + i) = h;
    }
}
struct WEnt { const float* p; unsigned long long off; int kd, n; };
struct WTab { WEnt e[15]; };
__global__ void wconv_all(WTab tab, __half* __restrict__ wp) {
    WEnt E = tab.e[blockIdx.z];
    int n0 = blockIdx.x * 32, k0 = blockIdx.y * 32;
    if (n0 >= E.n || k0 >= E.kd) return;
    __shared__ float tile[32][33];
    int tx = threadIdx.x, ty = threadIdx.y;
    for (int i = ty; i < 32; i += 8)
        tile[i][tx] = E.p[(size_t)(k0 + i) * E.n + n0 + tx];
    __syncthreads();
    __half* W = wp + E.off;
    for (int i = ty; i < 32; i += 8)
        W[(size_t)(n0 + i) * E.kd + k0 + tx] = __float2half(tile[tx][i]);
}

// ========================= TMA-fed 1xFP16 mma.sync GEMM core =========================
// CTA tile 128x128, K-chunk 64 (SW128), 256 threads = 8 warps, warp tile 64x32.
// 3 TMA stages, 2 CTAs/SM. Explicit per-stage phase cursors.
#define S_A 0
#define S_B 16384
#define STAGE_SZ 32768
#define CHUNK_BYTES 32768u
#define NSTAGE 3
#define SMEM_REQ 99392

__device__ __forceinline__ void compute_chunk(uint32_t st, int warp_m, int warp_n, int lane,
                                              float acc[4][4][4])
{
    const int lrow = lane & 7;
    const int lmat = lane >> 3;
#pragma unroll
    for (int ks = 0; ks < 4; ks++) {
        uint32_t bw[8];
#pragma unroll
        for (int p = 0; p < 2; p++) {
            int ntile = p * 2 + (lmat >> 1);
            int half_ = lmat & 1;
            uint32_t off = (uint32_t)((warp_n * 32 + ntile * 8 + lrow) * 128 + (ks * 16 + half_ * 8) * 2);
            uint32_t a = swz128(off);
            ldmx4(bw[p * 4 + 0], bw[p * 4 + 1], bw[p * 4 + 2], bw[p * 4 + 3], st + S_B + a);
        }
#pragma unroll
        for (int mt = 0; mt < 4; mt++) {
            uint32_t ar[4];
            uint32_t off = (uint32_t)((warp_m * 64 + mt * 16 + (lmat & 1) * 8 + lrow) * 128
                                      + (ks * 16 + (lmat >> 1) * 8) * 2);
            uint32_t a = swz128(off);
            ldmx4(ar[0], ar[1], ar[2], ar[3], st + S_A + a);
#pragma unroll
            for (int nt = 0; nt < 4; nt++)
                mma16816(acc[mt][nt], ar, bw[nt * 2], bw[nt * 2 + 1]);
        }
    }
}

// barriers: full[s]=mbar+s*8 (cnt1), empty[s]=mbar+24+s*8 (cnt 8)
#define PERS_INIT()                                                              \
    if (tid == 0) {                                                              \
        for (int s = 0; s < NSTAGE; s++) {                                       \
            MBARRIER_INIT(mbar + s * 8, 1);                                      \
            MBARRIER_INIT(mbar + 24 + s * 8, 8);                                 \
        }                                                                        \
    }                                                                            \
    __syncthreads();

// producer/consumer cursor state (registers)
struct Cur { int s; int ph[NSTAGE]; };
__device__ __forceinline__ void cur_init(Cur& c) { c.s = 0; c.ph[0] = c.ph[1] = c.ph[2] = 0; }
__device__ __forceinline__ void cur_adv(Cur& c) { c.s = (c.s == NSTAGE - 1) ? 0 : c.s + 1; }

// ---- persistent batched layer-1 GEMM: N=3328 = [y|d|z|t] ----
struct L1Out {
    __half* o[4];
    const float* bias[4];
};
__global__ void __launch_bounds__(256, 2)
gemmL1(const __grid_constant__ CUtensorMap tA, const __grid_constant__ CUtensorMap tB,
       L1Out O, const float* __restrict__ yv, const float* __restrict__ dv,
       const float* __restrict__ wyd, const int* __restrict__ posmap)
{
    extern __shared__ char smraw[];
    uint32_t sb = smem_u32(smraw);
    uint32_t ab = (sb + 1023u) & ~1023u;
    const uint32_t mbar = ab + NSTAGE * STAGE_SZ;
    const int tid = threadIdx.x;
    const int wid = tid >> 5;
    const int lane = tid & 31;
    const int warp_m = wid & 1;
    const int warp_n = wid >> 1;
    const int nc = 16;
    const int ntN = 26;
    const int nTiles = 128 * 26;

    PERS_INIT()

    int tiles_mine = 0;
    for (int t = blockIdx.x; t < nTiles; t += gridDim.x) tiles_mine++;
    const long total = (long)tiles_mine * nc;

    Cur P, C;       // producer, consumer
    cur_init(P); cur_init(C);
    bool pfirst[NSTAGE] = { true, true, true };
    int p_t = blockIdx.x, p_k = 0;
    if (tid == 0) {
        long lim = total < 2 ? total : 2;
        for (long i = 0; i < lim; i++) {
            uint32_t st_ = ab + P.s * STAGE_SZ;
            uint32_t mb_ = mbar + P.s * 8;
            MBARRIER_EXPECT_TX(mb_, CHUNK_BYTES);
            tma2d(st_ + S_A, &tA, p_k * 64, (p_t / ntN) * 128, mb_);
            tma2d(st_ + S_B, &tB, p_k * 64, (p_t % ntN) * 128, mb_);
            pfirst[P.s] = false;
            cur_adv(P);
            if (++p_k == nc) { p_k = 0; p_t += gridDim.x; }
        }
    }

    long g = 0;
    for (int t = blockIdx.x; t < nTiles; t += gridDim.x) {
        const int bm = (t / ntN) * 128;
        const int bnT = (t % ntN) * 128;
        const int seg = bnT >> 10;            // 0=y 1=d 2=z 3=t
        const int bn = bnT & 1023;
        float acc[4][4][4];
#pragma unroll
        for (int i = 0; i < 4; i++)
#pragma unroll
            for (int j = 0; j < 4; j++)
#pragma unroll
                for (int q = 0; q < 4; q++) acc[i][j][q] = 0.f;

        for (int ch = 0; ch < nc; ch++, g++) {
            MBARRIER_WAIT_PARITY(mbar + C.s * 8, C.ph[C.s]);
            C.ph[C.s] ^= 1;
            compute_chunk(ab + C.s * STAGE_SZ, warp_m, warp_n, lane, acc);
            if (lane == 0) MBARRIER_ARRIVE(mbar + 24 + C.s * 8);
            cur_adv(C);
            if (tid == 0 && g + 2 < total) {
                if (!pfirst[P.s]) { MBARRIER_WAIT_PARITY(mbar + 24 + P.s * 8, P.ph[P.s]); P.ph[P.s] ^= 1; }
                pfirst[P.s] = false;
                uint32_t st_ = ab + P.s * STAGE_SZ;
                uint32_t mb_ = mbar + P.s * 8;
                MBARRIER_EXPECT_TX(mb_, CHUNK_BYTES);
                tma2d(st_ + S_A, &tA, p_k * 64, (p_t / ntN) * 128, mb_);
                tma2d(st_ + S_B, &tB, p_k * 64, (p_t % ntN) * 128, mb_);
                cur_adv(P);
                if (++p_k == nc) { p_k = 0; p_t += gridDim.x; }
            }
        }

        __half* oh = O.o[seg];
        const float* bias = O.bias[seg];
        const bool isZ = (seg == 2);
        const int segN = (seg == 3) ? 256 : 1024;
        const int tgm = lane >> 2;
        const int tgn = (lane & 3) * 2;
#pragma unroll
        for (int mt = 0; mt < 4; mt++) {
#pragma unroll
            for (int dh = 0; dh < 2; dh++) {
                int m = bm + warp_m * 64 + mt * 16 + tgm + dh * 8;
                float ya = 0.f, da = 0.f;
                int mo = m;
                if (isZ) { ya = __ldg(yv + m); da = __ldg(dv + m); mo = __ldg(posmap + m); }
#pragma unroll
                for (int nt = 0; nt < 4; nt++) {
                    int n = bn + warp_n * 32 + nt * 8 + tgn;
                    float v0 = acc[mt][nt][dh * 2 + 0];
                    float v1 = acc[mt][nt][dh * 2 + 1];
                    float2 bb = *(const float2*)(bias + n);
                    v0 += bb.x; v1 += bb.y;
                    if (isZ) {
                        float2 w0 = *(const float2*)(wyd + n);
                        float2 w1 = *(const float2*)(wyd + 1024 + n);
                        v0 += ya * w0.x + da * w1.x;
                        v1 += ya * w0.y + da * w1.y;
                    }
                    v0 = elu_f(v0); v1 = elu_f(v1);
                    __half2 hp; hp.x = __float2half(v0); hp.y = __float2half(v1);
                    *(__half2*)(oh + (size_t)mo * segN + n) = hp;
                }
            }
        }
    }
}

// ---- persistent merged layer-2 GEMM: 3328 tiles = 3x1024 (y2,d2,z2; nc=16) + 256 (t2; nc=4) ----
__global__ void __launch_bounds__(256, 2)
gemmL2(const __grid_constant__ CUtensorMap tA0, const __grid_constant__ CUtensorMap tA1,
       const __grid_constant__ CUtensorMap tA2, const __grid_constant__ CUtensorMap tA3,
       const __grid_constant__ CUtensorMap tB0, const __grid_constant__ CUtensorMap tB1,
       const __grid_constant__ CUtensorMap tB2, const __grid_constant__ CUtensorMap tB3,
       const float* __restrict__ b0, const float* __restrict__ b1, const float* __restrict__ b2,
       const float* __restrict__ b3,
       float* __restrict__ fy, float* __restrict__ fd, __half* __restrict__ z2,
       float* __restrict__ ft)
{
    extern __shared__ char smraw[];
    uint32_t sb = smem_u32(smraw);
    uint32_t ab = (sb + 1023u) & ~1023u;
    const uint32_t mbar = ab + NSTAGE * STAGE_SZ;
    const int tid = threadIdx.x;
    const int wid = tid >> 5;
    const int lane = tid & 31;
    const int warp_m = wid & 1;
    const int warp_n = wid >> 1;
    const int nTiles = 3328;

    const CUtensorMap* Am[4] = { &tA0, &tA1, &tA2, &tA3 };
    const CUtensorMap* Bm[4] = { &tB0, &tB1, &tB2, &tB3 };
    const float* biases[4] = { b0, b1, b2, b3 };

    // tile decode: t<3072: seg=t>>10, ts=t&1023, bm=(ts>>3)*128, bn=(ts&7)*128, nc=16
    //              t>=3072: seg=3, ts=t-3072, bm=(ts>>1)*128, bn=(ts&1)*128, nc=4
    auto dec = [](int t, int& seg, int& bm, int& bn, int& nc) {
        if (t < 3072) { seg = t >> 10; int ts = t & 1023; bm = (ts >> 3) * 128; bn = (ts & 7) * 128; nc = 16; }
        else          { seg = 3; int ts = t - 3072; bm = (ts >> 1) * 128; bn = (ts & 1) * 128; nc = 4; }
    };

    PERS_INIT()

    long total = 0;
    for (int t = blockIdx.x; t < nTiles; t += gridDim.x) {
        int sg, bm_, bn_, nc_;
        dec(t, sg, bm_, bn_, nc_);
        total += nc_;
    }

    Cur P, C;
    cur_init(P); cur_init(C);
    bool pfirst[NSTAGE] = { true, true, true };
    int p_t = blockIdx.x, p_k = 0;
    int p_seg, p_bm, p_bn, p_nc;
    dec(p_t, p_seg, p_bm, p_bn, p_nc);
    if (tid == 0) {
        long lim = total < 2 ? total : 2;
        for (long i = 0; i < lim; i++) {
            uint32_t st_ = ab + P.s * STAGE_SZ;
            uint32_t mb_ = mbar + P.s * 8;
            MBARRIER_EXPECT_TX(mb_, CHUNK_BYTES);
            tma2d(st_ + S_A, Am[p_seg], p_k * 64, p_bm, mb_);
            tma2d(st_ + S_B, Bm[p_seg], p_k * 64, p_bn, mb_);
            pfirst[P.s] = false;
            cur_adv(P);
            if (++p_k == p_nc) { p_k = 0; p_t += gridDim.x; if (p_t < nTiles) dec(p_t, p_seg, p_bm, p_bn, p_nc); }
        }
    }

    long g = 0;
    for (int t = blockIdx.x; t < nTiles; t += gridDim.x) {
        int seg, bm, bn, nc;
        dec(t, seg, bm, bn, nc);
        float acc[4][4][4];
#pragma unroll
        for (int i = 0; i < 4; i++)
#pragma unroll
            for (int j = 0; j < 4; j++)
#pragma unroll
                for (int q = 0; q < 4; q++) acc[i][j][q] = 0.f;

        for (int ch = 0; ch < nc; ch++, g++) {
            MBARRIER_WAIT_PARITY(mbar + C.s * 8, C.ph[C.s]);
            C.ph[C.s] ^= 1;
            compute_chunk(ab + C.s * STAGE_SZ, warp_m, warp_n, lane, acc);
            if (lane == 0) MBARRIER_ARRIVE(mbar + 24 + C.s * 8);
            cur_adv(C);
            if (tid == 0 && g + 2 < total) {
                if (!pfirst[P.s]) { MBARRIER_WAIT_PARITY(mbar + 24 + P.s * 8, P.ph[P.s]); P.ph[P.s] ^= 1; }
                pfirst[P.s] = false;
                uint32_t st_ = ab + P.s * STAGE_SZ;
                uint32_t mb_ = mbar + P.s * 8;
                MBARRIER_EXPECT_TX(mb_, CHUNK_BYTES);
                tma2d(st_ + S_A, Am[p_seg], p_k * 64, p_bm, mb_);
                tma2d(st_ + S_B, Bm[p_seg], p_k * 64, p_bn, mb_);
                cur_adv(P);
                if (++p_k == p_nc) { p_k = 0; p_t += gridDim.x; if (p_t < nTiles) dec(p_t, p_seg, p_bm, p_bn, p_nc); }
            }
        }

        const float* bias = biases[seg];
        const int segN = (seg == 3) ? 256 : 1024;
        const int tgm = lane >> 2;
        const int tgn = (lane & 3) * 2;
#pragma unroll
        for (int mt = 0; mt < 4; mt++) {
#pragma unroll
            for (int dh = 0; dh < 2; dh++) {
                int m = bm + warp_m * 64 + mt * 16 + tgm + dh * 8;
#pragma unroll
                for (int nt = 0; nt < 4; nt++) {
                    int n = bn + warp_n * 32 + nt * 8 + tgn;
                    float v0 = acc[mt][nt][dh * 2 + 0];
                    float v1 = acc[mt][nt][dh * 2 + 1];
                    float2 bb = *(const float2*)(bias + n);
                    v0 = elu_f(v0 + bb.x); v1 = elu_f(v1 + bb.y);
                    if (seg == 2) {
                        __half2 hp; hp.x = __float2half(v0); hp.y = __float2half(v1);
                        *(__half2*)(z2 + (size_t)m * 1024 + n) = hp;
                    } else {
                        float* o = (seg == 0) ? fy : (seg == 1) ? fd : ft;
                        *(float2*)(o + (size_t)m * segN + n) = make_float2(v0, v1);
                    }
                }
            }
        }
    }
}

// ---- z head: grouped GEMM over gathered rows (non-persistent, 3-stage) ----
__global__ void __launch_bounds__(256, 2)
zheadT(const __grid_constant__ CUtensorMap tA, const __grid_constant__ CUtensorMap tB,
       const float* __restrict__ zhb, float* __restrict__ out)
{
    const int grp = blockIdx.z;
    const int cnt = g_cnt[grp];
    const int m0 = blockIdx.y * 128;
    if (m0 >= cnt) return;
    const int base = g_off[grp];
    const int bn = blockIdx.x * 128;
    const int brow = grp * 512 + bn;
    const int arow = base + m0;

    extern __shared__ char smraw[];
    uint32_t sb = smem_u32(smraw);
    uint32_t ab = (sb + 1023u) & ~1023u;
    const uint32_t mbar = ab + NSTAGE * STAGE_SZ;
    const int tid = threadIdx.x;
    const int wid = tid >> 5;
    const int lane = tid & 31;
    const int warp_m = wid & 1;
    const int warp_n = wid >> 1;

    PERS_INIT()

    if (tid == 0) {
        for (int p = 0; p < 2; p++) {
            uint32_t st = ab + p * STAGE_SZ;
            uint32_t mb = mbar + p * 8;
            MBARRIER_EXPECT_TX(mb, CHUNK_BYTES);
            tma2d(st + S_A, &tA, p * 64, arow, mb);
            tma2d(st + S_B, &tB, p * 64, brow, mb);
        }
    }

    float acc[4][4][4];
#pragma unroll
    for (int i = 0; i < 4; i++)
#pragma unroll
        for (int j = 0; j < 4; j++)
#pragma unroll
            for (int q = 0; q < 4; q++) acc[i][j][q] = 0.f;

    Cur P, C;
    cur_init(P); cur_init(C);
    P.s = 2;   // next stage to fill is 2 (0 and 1 prefilled)
    for (int ch = 0; ch < 16; ch++) {
        MBARRIER_WAIT_PARITY(mbar + C.s * 8, C.ph[C.s]);
        C.ph[C.s] ^= 1;
        compute_chunk(ab + C.s * STAGE_SZ, warp_m, warp_n, lane, acc);
        if (lane == 0) MBARRIER_ARRIVE(mbar + 24 + C.s * 8);
        cur_adv(C);
        if (tid == 0 && ch + 2 < 16) {
            if (ch >= 1) { MBARRIER_WAIT_PARITY(mbar + 24 + P.s * 8, P.ph[P.s]); P.ph[P.s] ^= 1; }
            uint32_t st = ab + P.s * STAGE_SZ;
            uint32_t mb = mbar + P.s * 8;
            MBARRIER_EXPECT_TX(mb, CHUNK_BYTES);
            tma2d(st + S_A, &tA, (ch + 2) * 64, arow, mb);
            tma2d(st + S_B, &tB, (ch + 2) * 64, brow, mb);
            cur_adv(P);
        }
    }

    const int tgm = lane >> 2;
    const int tgn = (lane & 3) * 2;
#pragma unroll
    for (int mt = 0; mt < 4; mt++) {
#pragma unroll
        for (int dh = 0; dh < 2; dh++) {
            int mloc = warp_m * 64 + mt * 16 + tgm + dh * 8;
            int gi = m0 + mloc;
            if (gi >= cnt) continue;
            int rg = g_ridx[base + gi];
            float* op = out + (size_t)rg * OUTC + 11;
#pragma unroll
            for (int nt = 0; nt < 4; nt++) {
                int n = bn + warp_n * 32 + nt * 8 + tgn;
                float v0 = acc[mt][nt][dh * 2 + 0] + __ldg(zhb + grp * 512 + n);
                float v1 = acc[mt][nt][dh * 2 + 1] + __ldg(zhb + grp * 512 + n + 1);
                if (n < 256) {
                    v0 = fminf(fmaxf(v0, -100.f), 100.f);
                    v1 = fminf(fmaxf(v1, -100.f), 100.f);
                } else {
                    v0 = fminf(softplus_f(v0) + 0.001f, 100.f);
                    v1 = fminf(softplus_f(v1) + 0.001f, 100.f);
                }
                op[n] = v0;
                op[n + 1] = v1;
            }
        }
    }
}

// ========================= small head kernels (fp32) =========================
__global__ void thead_kernel(const float* __restrict__ hid, const float* __restrict__ tw2,
                             const float* __restrict__ tb2, float* __restrict__ out)
{
    int w = (blockIdx.x * blockDim.x + threadIdx.x) >> 5;
    int lane = threadIdx.x & 31;
    if (w >= BATCH) return;
    const float* hr = hid + (size_t)w * 256;
    float acc[7] = {0.f, 0.f, 0.f, 0.f, 0.f, 0.f, 0.f};
    for (int k = lane; k < 256; k += 32) {
        float h = hr[k];
        const float* wr = tw2 + k * 7;
#pragma unroll
        for (int j = 0; j < 7; j++) acc[j] = fmaf(h, wr[j], acc[j]);
    }
#pragma unroll
    for (int j = 0; j < 7; j++)
        for (int o = 16; o > 0; o >>= 1) acc[j] += __shfl_xor_sync(0xffffffffu, acc[j], o);
    if (lane == 0) {
#pragma unroll
        for (int j = 0; j < 7; j++) {
            float v = elu_f(acc[j] + tb2[j]);
            out[(size_t)w * OUTC + j] = fminf(fmaxf(v, -10.f), 10.f);
        }
    }
}
__global__ void head2_kernel(const float* __restrict__ hid, const int* __restrict__ t,
                             const float* __restrict__ hW, const float* __restrict__ hb,
                             float* __restrict__ out, int col0)
{
    int w = (blockIdx.x * blockDim.x + threadIdx.x) >> 5;
    int lane = threadIdx.x & 31;
    if (w >= BATCH) return;
    int tt = t[w];
    const float*  hr = hid + (size_t)w * 1024;
    const float2* wp = (const float2*)(hW + (size_t)tt * 2048);
    float a0 = 0.f, a1 = 0.f;
    for (int k = lane; k < 1024; k += 32) {
        float h = hr[k];
        float2 ww = wp[k];
        a0 = fmaf(h, ww.x, a0);
        a1 = fmaf(h, ww.y, a1);
    }
    for (int o = 16; o > 0; o >>= 1) {
        a0 += __shfl_xor_sync(0xffffffffu, a0, o);
        a1 += __shfl_xor_sync(0xffffffffu, a1, o);
    }
    if (lane == 0) {
        float loc = fminf(fmaxf(a0 + hb[tt * 2 + 0], -1e6f), 1e6f);
        float sc  = fminf(softplus_f(a1 + hb[tt * 2 + 1]) + 1e-3f, 1e6f);
        out[(size_t)w * OUTC + col0]     = loc;
        out[(size_t)w * OUTC + col0 + 1] = sc;
    }
}

// ========================= host-side tensormap builder =========================
typedef CUresult (*PFN_tmap)(CUtensorMap*, CUtensorMapDataType, cuuint32_t, void*,
                             const cuuint64_t*, const cuuint64_t*, const cuuint32_t*,
                             const cuuint32_t*, CUtensorMapInterleave, CUtensorMapSwizzle,
                             CUtensorMapL2promotion, CUtensorMapFloatOOBfill);
static PFN_tmap tmap_fn() {
    static PFN_tmap fn = nullptr;
    if (!fn) {
        cudaDriverEntryPointQueryResult qr;
        cudaGetDriverEntryPointByVersion("cuTensorMapEncodeTiled", (void**)&fn, 12000,
                                         cudaEnableDefault, &qr);
    }
    return fn;
}
static void make_map(CUtensorMap* m, const __half* base, unsigned long long inner,
                     unsigned long long outer, unsigned box_in, unsigned box_out) {
    cuuint64_t dims[2] = { inner, outer };
    cuuint64_t strides[1] = { inner * 2 };
    cuuint32_t box[2] = { box_in, box_out };
    cuuint32_t es[2] = { 1, 1 };
    tmap_fn()(m, CU_TENSOR_MAP_DATA_TYPE_FLOAT16, 2, (void*)base, dims, strides, box, es,
              CU_TENSOR_MAP_INTERLEAVE_NONE, CU_TENSOR_MAP_SWIZZLE_128B,
              CU_TENSOR_MAP_L2_PROMOTION_L2_128B, CU_TENSOR_MAP_FLOAT_OOB_FILL_NONE);
}

// ========================= launch =========================
extern "C" void kernel_launch(void* const* d_in, const int* in_sizes, int n_in,
                              void* d_out, int out_size)
{
    const float* x   = (const float*)d_in[0];
    const int*   t   = (const int*)  d_in[1];
    const float* yv  = (const float*)d_in[2];
    const float* dv  = (const float*)d_in[3];
    const float* tw0 = (const float*)d_in[4];
    const float* tb0 = (const float*)d_in[5];
    const float* tw1 = (const float*)d_in[6];
    const float* tb1 = (const float*)d_in[7];
    const float* tw2 = (const float*)d_in[8];
    const float* tb2 = (const float*)d_in[9];
    const float* yw0 = (const float*)d_in[10];
    const float* yb0 = (const float*)d_in[11];
    const float* yw1 = (const float*)d_in[12];
    const float* yb1 = (const float*)d_in[13];
    const float* yhW = (const float*)d_in[14];
    const float* yhb = (const float*)d_in[15];
    const float* dw0 = (const float*)d_in[16];
    const float* db0 = (const float*)d_in[17];
    const float* dw1 = (const float*)d_in[18];
    const float* db1 = (const float*)d_in[19];
    const float* dhW = (const float*)d_in[20];
    const float* dhb = (const float*)d_in[21];
    const float* zw0 = (const float*)d_in[22];
    const float* zb0 = (const float*)d_in[23];
    const float* zw1 = (const float*)d_in[24];
    const float* zb1 = (const float*)d_in[25];
    const float* zhW = (const float*)d_in[26];
    const float* zhb = (const float*)d_in[27];
    float* out = (float*)d_out;

    __half *xh, *y1, *d1, *z1, *z2, *t1, *wh;
    float *fy, *fd, *ft;
    int *posmap;
    cudaGetSymbolAddress((void**)&xh, g_x);
    cudaGetSymbolAddress((void**)&y1, g_y1);
    cudaGetSymbolAddress((void**)&d1, g_d1);
    cudaGetSymbolAddress((void**)&z1, g_z1);
    cudaGetSymbolAddress((void**)&z2, g_z2);
    cudaGetSymbolAddress((void**)&t1, g_t1);
    cudaGetSymbolAddress((void**)&wh, g_wh);
    cudaGetSymbolAddress((void**)&fy, g_fy);
    cudaGetSymbolAddress((void**)&fd, g_fd);
    cudaGetSymbolAddress((void**)&ft, g_ft);
    cudaGetSymbolAddress((void**)&posmap, g_pos);

    static cudaStream_t s1, s2, s3;
    static cudaEvent_t eL2, eJ1, eJ2, eJ3;
    static bool init = false;
    if (!init) {
        cudaStreamCreateWithFlags(&s1, cudaStreamNonBlocking);
        cudaStreamCreateWithFlags(&s2, cudaStreamNonBlocking);
        cudaStreamCreateWithFlags(&s3, cudaStreamNonBlocking);
        cudaEventCreateWithFlags(&eL2, cudaEventDisableTiming);
        cudaEventCreateWithFlags(&eJ1, cudaEventDisableTiming);
        cudaEventCreateWithFlags(&eJ2, cudaEventDisableTiming);
        cudaEventCreateWithFlags(&eJ3, cudaEventDisableTiming);
        cudaFuncSetAttribute((const void*)gemmL1, cudaFuncAttributeMaxDynamicSharedMemorySize, SMEM_REQ);
        cudaFuncSetAttribute((const void*)gemmL2, cudaFuncAttributeMaxDynamicSharedMemorySize, SMEM_REQ);
        cudaFuncSetAttribute((const void*)zheadT, cudaFuncAttributeMaxDynamicSharedMemorySize, SMEM_REQ);
        init = true;
    }

    static CUtensorMap M[12];
    make_map(&M[0],  xh, 1024, BATCH, 64, 128);
    make_map(&M[1],  y1, 1024, BATCH, 64, 128);
    make_map(&M[2],  d1, 1024, BATCH, 64, 128);
    make_map(&M[3],  z1, 1024, BATCH, 64, 128);
    make_map(&M[4],  z2, 1024, BATCH, 64, 128);
    make_map(&M[5],  t1, 256,  BATCH, 64, 128);
    make_map(&M[6],  wh + OFF_TW1, 256,  256,  64, 128);
    make_map(&M[7],  wh + OFF_L1,  1024, 3328, 64, 128);
    make_map(&M[8],  wh + OFF_YW1, 1024, 1024, 64, 128);
    make_map(&M[9],  wh + OFF_DW1, 1024, 1024, 64, 128);
    make_map(&M[10], wh + OFF_ZW1, 1024, 1024, 64, 128);
    make_map(&M[11], wh + OFF_ZHW, 1024, 3584, 64, 128);

    bucket_all<<<1, 1024>>>(t);
    xconv_kernel<<<(BATCH * 1024 / 2 + 255) / 256, 256>>>(x, xh, BATCH * 1024);
    WTab tab;
    tab.e[0]  = { tw1,            OFF_TW1,               256,  256 };
    tab.e[1]  = { yw0,            OFF_L1,                1024, 1024 };
    tab.e[2]  = { dw0,            OFF_L1 + 1048576ull,   1024, 1024 };
    tab.e[3]  = { zw0 + 2 * 1024, OFF_L1 + 2097152ull,   1024, 1024 };
    tab.e[4]  = { tw0,            OFF_L1 + 3145728ull,   1024, 256 };
    tab.e[5]  = { yw1,            OFF_YW1,               1024, 1024 };
    tab.e[6]  = { dw1,            OFF_DW1,               1024, 1024 };
    tab.e[7]  = { zw1,            OFF_ZW1,               1024, 1024 };
    for (int g = 0; g < 7; g++)
        tab.e[8 + g] = { zhW + (size_t)g * 1024 * 512,
                         (unsigned long long)(OFF_ZHW + (size_t)g * 524288), 1024, 512 };
    wconv_all<<<dim3(32, 32, 15), dim3(32, 8)>>>(tab, wh);

    // ---- L1 mega (y|d|z|t layer-1), 2 CTAs/SM ----
    L1Out O;
    O.o[0] = y1; O.bias[0] = yb0;
    O.o[1] = d1; O.bias[1] = db0;
    O.o[2] = z1; O.bias[2] = zb0;
    O.o[3] = t1; O.bias[3] = tb0;
    gemmL1<<<296, 256, SMEM_REQ>>>(M[0], M[7], O, yv, dv, zw0, posmap);

    // ---- L2 mega (y2 | d2 | z2 | t2) ----
    gemmL2<<<296, 256, SMEM_REQ>>>(M[1], M[2], M[3], M[5],
                                   M[8], M[9], M[10], M[6],
                                   yb1, db1, zb1, tb1, fy, fd, z2, ft);
    cudaEventRecord(eL2, 0);

    const int headBlocks = (BATCH * 32) / 256;

    // ---- tails on streams ----
    cudaStreamWaitEvent(s1, eL2, 0);
    thead_kernel<<<headBlocks, 256, 0, s1>>>(ft, tw2, tb2, out);
    cudaEventRecord(eJ1, s1);

    cudaStreamWaitEvent(s2, eL2, 0);
    head2_kernel<<<headBlocks, 256, 0, s2>>>(fy, t, yhW, yhb, out, 7);
    head2_kernel<<<headBlocks, 256, 0, s2>>>(fd, t, dhW, dhb, out, 9);
    cudaEventRecord(eJ2, s2);

    cudaStreamWaitEvent(s3, eL2, 0);
    zheadT<<<dim3(4, 128, 7), 256, SMEM_REQ, s3>>>(M[4], M[11], zhb, out);
    cudaEventRecord(eJ3, s3);

    cudaStreamWaitEvent(0, eJ1, 0);
    cudaStreamWaitEvent(0, eJ2, 0);
    cudaStreamWaitEvent(0, eJ3, 0);
}

// round 17
// speedup vs baseline: 1.1358x; 1.1358x over previous
#include <cuda_runtime.h>
#include <cuda.h>
#include <cuda_fp16.h>
#include <cstdint>
#include <math.h>

#define BATCH 16384
#define OUTC  523   // 7 + 4 + 512

// ========================= PTX helpers =========================
__device__ __forceinline__ uint32_t smem_u32(const void* p) {
    uint32_t a;
    asm("{ .reg .u64 t; cvta.to.shared.u64 t, %1; cvt.u32.u64 %0, t; }" : "=r"(a) : "l"(p));
    return a;
}
__device__ __forceinline__ void ldmx4(uint32_t& r0, uint32_t& r1, uint32_t& r2, uint32_t& r3, uint32_t addr) {
    asm volatile("ldmatrix.sync.aligned.m8n8.x4.shared.b16 {%0,%1,%2,%3}, [%4];"
                 : "=r"(r0), "=r"(r1), "=r"(r2), "=r"(r3) : "r"(addr));
}
__device__ __forceinline__ void mma16816(float* c, const uint32_t* a, uint32_t b0, uint32_t b1) {
    asm volatile("mma.sync.aligned.m16n8k16.row.col.f32.f16.f16.f32 "
                 "{%0,%1,%2,%3}, {%4,%5,%6,%7}, {%8,%9}, {%0,%1,%2,%3};"
                 : "+f"(c[0]), "+f"(c[1]), "+f"(c[2]), "+f"(c[3])
                 : "r"(a[0]), "r"(a[1]), "r"(a[2]), "r"(a[3]), "r"(b0), "r"(b1));
}
__device__ __forceinline__ uint32_t swz128(uint32_t off) { return off ^ ((off >> 3) & 0x70); }

__device__ __forceinline__ void tma2d(uint32_t dst, const CUtensorMap* map, int cx, int cy, uint32_t mbar) {
    asm volatile("cp.async.bulk.tensor.2d.shared::cta.global.tile.mbarrier::complete_tx::bytes "
                 "[%0], [%1, {%2, %3}], [%4];"
                 :: "r"(dst), "l"(map), "r"(cx), "r"(cy), "r"(mbar) : "memory");
}
#define MBARRIER_INIT(addr, cnt) \
    asm volatile("mbarrier.init.shared.b64 [%0], %1;" :: "r"((uint32_t)(addr)), "r"((uint32_t)(cnt)) : "memory")
#define MBARRIER_ARRIVE(addr) \
    asm volatile("mbarrier.arrive.shared.b64 _, [%0];" :: "r"((uint32_t)(addr)) : "memory")
#define MBARRIER_EXPECT_TX(addr, bytes) \
    asm volatile("mbarrier.arrive.expect_tx.shared.b64 _, [%0], %1;" \
        :: "r"((uint32_t)(addr)), "r"((uint32_t)(bytes)) : "memory")
#define MBARRIER_WAIT_PARITY(mbar_smem_addr, phase_parity) do { \
    uint32_t _mbar = (uint32_t)(mbar_smem_addr); \
    uint32_t _parity = (uint32_t)(phase_parity); \
    uint32_t _done; \
    asm volatile("{\n\t.reg .pred p;\n\t" \
        "mbarrier.try_wait.parity.acquire.cta.shared::cta.b64 p, [%1], %2;\n\t" \
        "selp.b32 %0, 1, 0, p;\n\t}" : "=r"(_done) : "r"(_mbar), "r"(_parity) : "memory"); \
    if (!_done) { \
        asm volatile("{\n\t.reg .pred P1;\n\t" \
            "WAIT_LOOP_%=:\n\t" \
            "mbarrier.try_wait.parity.acquire.cta.shared::cta.b64 P1, [%0], %1, 0x989680;\n\t" \
            "@P1 bra.uni WAIT_DONE_%=;\n\t" \
            "bra.uni WAIT_LOOP_%=;\n\t" \
            "WAIT_DONE_%=:\n\t}" :: "r"(_mbar), "r"(_parity) : "memory"); \
    } \
} while(0)

// ========================= scratch =========================
__device__ __align__(1024) __half g_x[BATCH * 1024];
__device__ __align__(1024) __half g_y1[BATCH * 1024];
__device__ __align__(1024) __half g_d1[BATCH * 1024];
__device__ __align__(1024) __half g_z1[BATCH * 1024];   // bucket order
__device__ __align__(1024) __half g_z2[BATCH * 1024];   // bucket order
__device__ __align__(1024) __half g_t1[BATCH * 256];
__device__ __half g_fy[BATCH * 1024];
__device__ __half g_fd[BATCH * 1024];
__device__ __half g_ft[BATCH * 256];
__device__ __align__(1024) __half g_wh[10300000];       // single-fp16 weight pool
__device__ int g_ridx[BATCH];
__device__ int g_pos[BATCH];
__device__ int g_cnt[8];
__device__ int g_off[8];

// weight-pool offsets (elements)
#define OFF_TW1 0             // [256,256]
#define OFF_L1  65536         // [3328,1024]: yw0|dw0|zw0'|tw0
#define OFF_YW1 3473408
#define OFF_DW1 4521984
#define OFF_ZW1 5570560
#define OFF_ZHW 6619136       // [3584,1024]

__device__ __forceinline__ float elu_f(float v) { return v > 0.f ? v : expm1f(v); }
__device__ __forceinline__ float softplus_f(float v) {
    return fmaxf(v, 0.f) + log1pf(expf(-fabsf(v)));
}

// ========================= fused bucketing =========================
__global__ void bucket_all(const int* __restrict__ t) {
    __shared__ int scnt[8];
    __shared__ int scur[8];
    int tid = threadIdx.x;
    if (tid < 8) scnt[tid] = 0;
    __syncthreads();
    for (int i = tid; i < BATCH; i += 1024) atomicAdd(&scnt[t[i]], 1);
    __syncthreads();
    if (tid == 0) {
        int s = 0;
        for (int k = 0; k < 7; k++) { g_cnt[k] = scnt[k]; g_off[k] = s; scur[k] = s; s += scnt[k]; }
    }
    __syncthreads();
    for (int i = tid; i < BATCH; i += 1024) {
        int p = atomicAdd(&scur[t[i]], 1);
        g_ridx[p] = i;
        g_pos[i] = p;
    }
}

// ========================= preprocessing =========================
__global__ void xconv_kernel(const float* __restrict__ x, __half* __restrict__ o, int n) {
    int i = (blockIdx.x * blockDim.x + threadIdx.x) * 2;
    if (i < n) {
        float2 v = *(const float2*)(x + i);
        __half2 h; h.x = __float2half(v.x); h.y = __float2half(v.y);
        *(__half2*)(o + i) = h;
    }
}
struct WEnt { const float* p; unsigned long long off; int kd, n; };
struct WTab { WEnt e[15]; };
__global__ void wconv_all(WTab tab, __half* __restrict__ wp) {
    WEnt E = tab.e[blockIdx.z];
    int n0 = blockIdx.x * 32, k0 = blockIdx.y * 32;
    if (n0 >= E.n || k0 >= E.kd) return;
    __shared__ float tile[32][33];
    int tx = threadIdx.x, ty = threadIdx.y;
    for (int i = ty; i < 32; i += 8)
        tile[i][tx] = E.p[(size_t)(k0 + i) * E.n + n0 + tx];
    __syncthreads();
    __half* W = wp + E.off;
    for (int i = ty; i < 32; i += 8)
        W[(size_t)(n0 + i) * E.kd + k0 + tx] = __float2half(tile[tx][i]);
}

// ========================= TMA-fed 1xFP16 mma.sync GEMM core =========================
// CTA tile 256x128, K-chunk 64 (SW128), 512 threads = 16 warps, warp tile 64x32.
// Plain fp16 GEMM, fp32 accumulate. Persistent tile loop, 4 TMA stages.
#define S_A 0
#define S_B 32768
#define STAGE_SZ 49152
#define CHUNK_BYTES 49152u
#define NSTAGE 4
#define SMEM_REQ 198688

__device__ __forceinline__ void compute_chunk(uint32_t st, int warp_m, int warp_n, int lane,
                                              float acc[4][4][4])
{
    const int lrow = lane & 7;
    const int lmat = lane >> 3;
#pragma unroll
    for (int ks = 0; ks < 4; ks++) {
        uint32_t bw[8];
#pragma unroll
        for (int p = 0; p < 2; p++) {
            int ntile = p * 2 + (lmat >> 1);
            int half_ = lmat & 1;
            uint32_t off = (uint32_t)((warp_n * 32 + ntile * 8 + lrow) * 128 + (ks * 16 + half_ * 8) * 2);
            uint32_t a = swz128(off);
            ldmx4(bw[p * 4 + 0], bw[p * 4 + 1], bw[p * 4 + 2], bw[p * 4 + 3], st + S_B + a);
        }
#pragma unroll
        for (int mt = 0; mt < 4; mt++) {
            uint32_t ar[4];
            uint32_t off = (uint32_t)((warp_m * 64 + mt * 16 + (lmat & 1) * 8 + lrow) * 128
                                      + (ks * 16 + (lmat >> 1) * 8) * 2);
            uint32_t a = swz128(off);
            ldmx4(ar[0], ar[1], ar[2], ar[3], st + S_A + a);
#pragma unroll
            for (int nt = 0; nt < 4; nt++)
                mma16816(acc[mt][nt], ar, bw[nt * 2], bw[nt * 2 + 1]);
        }
    }
}

#define PERS_INIT()                                                              \
    if (tid == 0) {                                                              \
        for (int s = 0; s < NSTAGE; s++) {                                       \
            MBARRIER_INIT(mbar + s * 8, 1);                                      \
            MBARRIER_INIT(mbar + 32 + s * 8, 16);                                \
        }                                                                        \
    }                                                                            \
    __syncthreads();

// ---- persistent batched layer-1 GEMM: N=3328 = [y|d|z|t] ----
struct L1Out {
    __half* o[4];
    const float* bias[4];
};
__global__ void __launch_bounds__(512, 1)
gemmL1(const __grid_constant__ CUtensorMap tA, const __grid_constant__ CUtensorMap tB,
       L1Out O, const float* __restrict__ yv, const float* __restrict__ dv,
       const float* __restrict__ wyd, const int* __restrict__ posmap)
{
    extern __shared__ char smraw[];
    uint32_t sb = smem_u32(smraw);
    uint32_t ab = (sb + 1023u) & ~1023u;
    const uint32_t mbar = ab + NSTAGE * STAGE_SZ;
    const int tid = threadIdx.x;
    const int wid = tid >> 5;
    const int lane = tid & 31;
    const int warp_m = wid & 3;
    const int warp_n = wid >> 2;
    const int nc = 16;
    const int ntN = 26;
    const int nTiles = 26 * 64;

    PERS_INIT()

    int tiles_mine = 0;
    for (int t = blockIdx.x; t < nTiles; t += gridDim.x) tiles_mine++;
    const long total = (long)tiles_mine * nc;

    int p_t = blockIdx.x, p_k = 0;
    if (tid == 0) {
        long lim = total < 3 ? total : 3;
        for (long i = 0; i < lim; i++) {
            uint32_t st_ = ab + (int)i * STAGE_SZ;
            uint32_t mb_ = mbar + (int)i * 8;
            MBARRIER_EXPECT_TX(mb_, CHUNK_BYTES);
            tma2d(st_ + S_A, &tA, p_k * 64, (p_t / ntN) * 256, mb_);
            tma2d(st_ + S_B, &tB, p_k * 64, (p_t % ntN) * 128, mb_);
            if (++p_k == nc) { p_k = 0; p_t += gridDim.x; }
        }
    }

    long g = 0;
    for (int t = blockIdx.x; t < nTiles; t += gridDim.x) {
        const int bm = (t / ntN) * 256;
        const int bnT = (t % ntN) * 128;
        const int seg = bnT >> 10;            // 0=y 1=d 2=z 3=t
        const int bn = bnT & 1023;
        float acc[4][4][4];
#pragma unroll
        for (int i = 0; i < 4; i++)
#pragma unroll
            for (int j = 0; j < 4; j++)
#pragma unroll
                for (int q = 0; q < 4; q++) acc[i][j][q] = 0.f;

        for (int ch = 0; ch < nc; ch++, g++) {
            int s = (int)(g & 3);
            MBARRIER_WAIT_PARITY(mbar + s * 8, (int)((g >> 2) & 1));
            compute_chunk(ab + s * STAGE_SZ, warp_m, warp_n, lane, acc);
            if (lane == 0) MBARRIER_ARRIVE(mbar + 32 + s * 8);
            if (tid == 0) {
                long j = g + 3;
                if (j < total) {
                    int s3 = (int)(j & 3);
                    if (j >= 4) MBARRIER_WAIT_PARITY(mbar + 32 + s3 * 8, (int)(((j >> 2) - 1) & 1));
                    uint32_t st_ = ab + s3 * STAGE_SZ;
                    uint32_t mb_ = mbar + s3 * 8;
                    MBARRIER_EXPECT_TX(mb_, CHUNK_BYTES);
                    tma2d(st_ + S_A, &tA, p_k * 64, (p_t / ntN) * 256, mb_);
                    tma2d(st_ + S_B, &tB, p_k * 64, (p_t % ntN) * 128, mb_);
                    if (++p_k == nc) { p_k = 0; p_t += gridDim.x; }
                }
            }
        }

        __half* oh = O.o[seg];
        const float* bias = O.bias[seg];
        const bool isZ = (seg == 2);
        const int segN = (seg == 3) ? 256 : 1024;
        const int tgm = lane >> 2;
        const int tgn = (lane & 3) * 2;
#pragma unroll
        for (int mt = 0; mt < 4; mt++) {
#pragma unroll
            for (int dh = 0; dh < 2; dh++) {
                int m = bm + warp_m * 64 + mt * 16 + tgm + dh * 8;
                float ya = 0.f, da = 0.f;
                int mo = m;
                if (isZ) { ya = __ldg(yv + m); da = __ldg(dv + m); mo = __ldg(posmap + m); }
#pragma unroll
                for (int nt = 0; nt < 4; nt++) {
                    int n = bn + warp_n * 32 + nt * 8 + tgn;
                    float v0 = acc[mt][nt][dh * 2 + 0];
                    float v1 = acc[mt][nt][dh * 2 + 1];
                    float2 bb = *(const float2*)(bias + n);
                    v0 += bb.x; v1 += bb.y;
                    if (isZ) {
                        float2 w0 = *(const float2*)(wyd + n);
                        float2 w1 = *(const float2*)(wyd + 1024 + n);
                        v0 += ya * w0.x + da * w1.x;
                        v1 += ya * w0.y + da * w1.y;
                    }
                    v0 = elu_f(v0); v1 = elu_f(v1);
                    __half2 hp; hp.x = __float2half(v0); hp.y = __float2half(v1);
                    *(__half2*)(oh + (size_t)mo * segN + n) = hp;
                }
            }
        }
    }
}

// ---- persistent merged layer-2 GEMM: 1664 tiles = 3x512 (y2,d2,z2; nc=16) + 128 (t2; nc=4) ----
__global__ void __launch_bounds__(512, 1)
gemmL2(const __grid_constant__ CUtensorMap tA0, const __grid_constant__ CUtensorMap tA1,
       const __grid_constant__ CUtensorMap tA2, const __grid_constant__ CUtensorMap tA3,
       const __grid_constant__ CUtensorMap tB0, const __grid_constant__ CUtensorMap tB1,
       const __grid_constant__ CUtensorMap tB2, const __grid_constant__ CUtensorMap tB3,
       const float* __restrict__ b0, const float* __restrict__ b1, const float* __restrict__ b2,
       const float* __restrict__ b3,
       __half* __restrict__ fy, __half* __restrict__ fd, __half* __restrict__ z2,
       __half* __restrict__ ft)
{
    extern __shared__ char smraw[];
    uint32_t sb = smem_u32(smraw);
    uint32_t ab = (sb + 1023u) & ~1023u;
    const uint32_t mbar = ab + NSTAGE * STAGE_SZ;
    const int tid = threadIdx.x;
    const int wid = tid >> 5;
    const int lane = tid & 31;
    const int warp_m = wid & 3;
    const int warp_n = wid >> 2;
    const int nTiles = 1664;

    const CUtensorMap* Am[4] = { &tA0, &tA1, &tA2, &tA3 };
    const CUtensorMap* Bm[4] = { &tB0, &tB1, &tB2, &tB3 };
    const float* biases[4] = { b0, b1, b2, b3 };
    __half* outs[4] = { fy, fd, z2, ft };

    auto dec = [](int t, int& seg, int& bm, int& bn, int& nc) {
        if (t < 1536) { seg = t >> 9; int ts = t & 511; bm = (ts >> 3) * 256; bn = (ts & 7) * 128; nc = 16; }
        else          { seg = 3; int ts = t - 1536; bm = (ts >> 1) * 256; bn = (ts & 1) * 128; nc = 4; }
    };

    PERS_INIT()

    long total = 0;
    for (int t = blockIdx.x; t < nTiles; t += gridDim.x) {
        int sg, bm_, bn_, nc_;
        dec(t, sg, bm_, bn_, nc_);
        total += nc_;
    }

    int p_t = blockIdx.x, p_k = 0;
    int p_seg, p_bm, p_bn, p_nc;
    dec(p_t, p_seg, p_bm, p_bn, p_nc);
    if (tid == 0) {
        long lim = total < 3 ? total : 3;
        for (long i = 0; i < lim; i++) {
            uint32_t st_ = ab + (int)i * STAGE_SZ;
            uint32_t mb_ = mbar + (int)i * 8;
            MBARRIER_EXPECT_TX(mb_, CHUNK_BYTES);
            tma2d(st_ + S_A, Am[p_seg], p_k * 64, p_bm, mb_);
            tma2d(st_ + S_B, Bm[p_seg], p_k * 64, p_bn, mb_);
            if (++p_k == p_nc) { p_k = 0; p_t += gridDim.x; if (p_t < nTiles) dec(p_t, p_seg, p_bm, p_bn, p_nc); }
        }
    }

    long g = 0;
    for (int t = blockIdx.x; t < nTiles; t += gridDim.x) {
        int seg, bm, bn, nc;
        dec(t, seg, bm, bn, nc);
        float acc[4][4][4];
#pragma unroll
        for (int i = 0; i < 4; i++)
#pragma unroll
            for (int j = 0; j < 4; j++)
#pragma unroll
                for (int q = 0; q < 4; q++) acc[i][j][q] = 0.f;

        for (int ch = 0; ch < nc; ch++, g++) {
            int s = (int)(g & 3);
            MBARRIER_WAIT_PARITY(mbar + s * 8, (int)((g >> 2) & 1));
            compute_chunk(ab + s * STAGE_SZ, warp_m, warp_n, lane, acc);
            if (lane == 0) MBARRIER_ARRIVE(mbar + 32 + s * 8);
            if (tid == 0) {
                long j = g + 3;
                if (j < total) {
                    int s3 = (int)(j & 3);
                    if (j >= 4) MBARRIER_WAIT_PARITY(mbar + 32 + s3 * 8, (int)(((j >> 2) - 1) & 1));
                    uint32_t st_ = ab + s3 * STAGE_SZ;
                    uint32_t mb_ = mbar + s3 * 8;
                    MBARRIER_EXPECT_TX(mb_, CHUNK_BYTES);
                    tma2d(st_ + S_A, Am[p_seg], p_k * 64, p_bm, mb_);
                    tma2d(st_ + S_B, Bm[p_seg], p_k * 64, p_bn, mb_);
                    if (++p_k == p_nc) { p_k = 0; p_t += gridDim.x; if (p_t < nTiles) dec(p_t, p_seg, p_bm, p_bn, p_nc); }
                }
            }
        }

        const float* bias = biases[seg];
        __half* oh = outs[seg];
        const int segN = (seg == 3) ? 256 : 1024;
        const int tgm = lane >> 2;
        const int tgn = (lane & 3) * 2;
#pragma unroll
        for (int mt = 0; mt < 4; mt++) {
#pragma unroll
            for (int dh = 0; dh < 2; dh++) {
                int m = bm + warp_m * 64 + mt * 16 + tgm + dh * 8;
#pragma unroll
                for (int nt = 0; nt < 4; nt++) {
                    int n = bn + warp_n * 32 + nt * 8 + tgn;
                    float v0 = acc[mt][nt][dh * 2 + 0];
                    float v1 = acc[mt][nt][dh * 2 + 1];
                    float2 bb = *(const float2*)(bias + n);
                    v0 = elu_f(v0 + bb.x); v1 = elu_f(v1 + bb.y);
                    __half2 hp; hp.x = __float2half(v0); hp.y = __float2half(v1);
                    *(__half2*)(oh + (size_t)m * segN + n) = hp;
                }
            }
        }
    }
}

// ---- z head: grouped GEMM over gathered rows ----
__global__ void __launch_bounds__(512, 1)
zheadT(const __grid_constant__ CUtensorMap tA, const __grid_constant__ CUtensorMap tB,
       const float* __restrict__ zhb, float* __restrict__ out)
{
    const int grp = blockIdx.z;
    const int cnt = g_cnt[grp];
    const int m0 = blockIdx.y * 256;
    if (m0 >= cnt) return;
    const int base = g_off[grp];
    const int bn = blockIdx.x * 128;
    const int brow = grp * 512 + bn;
    const int arow = base + m0;

    extern __shared__ char smraw[];
    uint32_t sb = smem_u32(smraw);
    uint32_t ab = (sb + 1023u) & ~1023u;
    const uint32_t mbar = ab + NSTAGE * STAGE_SZ;
    const int tid = threadIdx.x;
    const int wid = tid >> 5;
    const int lane = tid & 31;
    const int warp_m = wid & 3;
    const int warp_n = wid >> 2;

    PERS_INIT()

    if (tid == 0) {
        for (int p = 0; p < 3; p++) {
            uint32_t st = ab + p * STAGE_SZ;
            uint32_t mb = mbar + p * 8;
            MBARRIER_EXPECT_TX(mb, CHUNK_BYTES);
            tma2d(st + S_A, &tA, p * 64, arow, mb);
            tma2d(st + S_B, &tB, p * 64, brow, mb);
        }
    }

    float acc[4][4][4];
#pragma unroll
    for (int i = 0; i < 4; i++)
#pragma unroll
        for (int j = 0; j < 4; j++)
#pragma unroll
            for (int q = 0; q < 4; q++) acc[i][j][q] = 0.f;

    for (int ch = 0; ch < 16; ch++) {
        int s = ch & 3;
        MBARRIER_WAIT_PARITY(mbar + s * 8, (ch >> 2) & 1);
        compute_chunk(ab + s * STAGE_SZ, warp_m, warp_n, lane, acc);
        if (lane == 0) MBARRIER_ARRIVE(mbar + 32 + s * 8);
        if (tid == 0 && ch + 3 < 16) {
            int s3 = (ch + 3) & 3;
            if (ch >= 1) MBARRIER_WAIT_PARITY(mbar + 32 + s3 * 8, (((ch + 3) >> 2) - 1) & 1);
            uint32_t st = ab + s3 * STAGE_SZ;
            uint32_t mb = mbar + s3 * 8;
            int k0 = (ch + 3) * 64;
            MBARRIER_EXPECT_TX(mb, CHUNK_BYTES);
            tma2d(st + S_A, &tA, k0, arow, mb);
            tma2d(st + S_B, &tB, k0, brow, mb);
        }
    }

    const int tgm = lane >> 2;
    const int tgn = (lane & 3) * 2;
#pragma unroll
    for (int mt = 0; mt < 4; mt++) {
#pragma unroll
        for (int dh = 0; dh < 2; dh++) {
            int mloc = warp_m * 64 + mt * 16 + tgm + dh * 8;
            int gi = m0 + mloc;
            if (gi >= cnt) continue;
            int rg = g_ridx[base + gi];
            float* op = out + (size_t)rg * OUTC + 11;
#pragma unroll
            for (int nt = 0; nt < 4; nt++) {
                int n = bn + warp_n * 32 + nt * 8 + tgn;
                float v0 = acc[mt][nt][dh * 2 + 0] + __ldg(zhb + grp * 512 + n);
                float v1 = acc[mt][nt][dh * 2 + 1] + __ldg(zhb + grp * 512 + n + 1);
                if (n < 256) {
                    v0 = fminf(fmaxf(v0, -100.f), 100.f);
                    v1 = fminf(fmaxf(v1, -100.f), 100.f);
                } else {
                    v0 = fminf(softplus_f(v0) + 0.001f, 100.f);
                    v1 = fminf(softplus_f(v1) + 0.001f, 100.f);
                }
                op[n] = v0;
                op[n + 1] = v1;
            }
        }
    }
}

// ========================= small head kernels (fp16 input, fp32 math) =========================
__global__ void thead_kernel(const __half* __restrict__ hid, const float* __restrict__ tw2,
                             const float* __restrict__ tb2, float* __restrict__ out)
{
    int w = (blockIdx.x * blockDim.x + threadIdx.x) >> 5;
    int lane = threadIdx.x & 31;
    if (w >= BATCH) return;
    const __half* hr = hid + (size_t)w * 256;
    float acc[7] = {0.f, 0.f, 0.f, 0.f, 0.f, 0.f, 0.f};
    for (int k = lane; k < 256; k += 32) {
        float h = __half2float(hr[k]);
        const float* wr = tw2 + k * 7;
#pragma unroll
        for (int j = 0; j < 7; j++) acc[j] = fmaf(h, wr[j], acc[j]);
    }
#pragma unroll
    for (int j = 0; j < 7; j++)
        for (int o = 16; o > 0; o >>= 1) acc[j] += __shfl_xor_sync(0xffffffffu, acc[j], o);
    if (lane == 0) {
#pragma unroll
        for (int j = 0; j < 7; j++) {
            float v = elu_f(acc[j] + tb2[j]);
            out[(size_t)w * OUTC + j] = fminf(fmaxf(v, -10.f), 10.f);
        }
    }
}
__global__ void head2_kernel(const __half* __restrict__ hid, const int* __restrict__ t,
                             const float* __restrict__ hW, const float* __restrict__ hb,
                             float* __restrict__ out, int col0)
{
    int w = (blockIdx.x * blockDim.x + threadIdx.x) >> 5;
    int lane = threadIdx.x & 31;
    if (w >= BATCH) return;
    int tt = t[w];
    const __half2* hr = (const __half2*)(hid + (size_t)w * 1024);
    const float2*  wp = (const float2*)(hW + (size_t)tt * 2048);
    float a0 = 0.f, a1 = 0.f;
    for (int k = lane; k < 512; k += 32) {
        __half2 h2 = hr[k];
        float hx = __half2float(h2.x), hy = __half2float(h2.y);
        float2 w0 = wp[k * 2];
        float2 w1 = wp[k * 2 + 1];
        a0 += hx * w0.x + hy * w1.x;
        a1 += hx * w0.y + hy * w1.y;
    }
    for (int o = 16; o > 0; o >>= 1) {
        a0 += __shfl_xor_sync(0xffffffffu, a0, o);
        a1 += __shfl_xor_sync(0xffffffffu, a1, o);
    }
    if (lane == 0) {
        float loc = fminf(fmaxf(a0 + hb[tt * 2 + 0], -1e6f), 1e6f);
        float sc  = fminf(softplus_f(a1 + hb[tt * 2 + 1]) + 1e-3f, 1e6f);
        out[(size_t)w * OUTC + col0]     = loc;
        out[(size_t)w * OUTC + col0 + 1] = sc;
    }
}

// ========================= host-side tensormap builder =========================
typedef CUresult (*PFN_tmap)(CUtensorMap*, CUtensorMapDataType, cuuint32_t, void*,
                             const cuuint64_t*, const cuuint64_t*, const cuuint32_t*,
                             const cuuint32_t*, CUtensorMapInterleave, CUtensorMapSwizzle,
                             CUtensorMapL2promotion, CUtensorMapFloatOOBfill);
static PFN_tmap tmap_fn() {
    static PFN_tmap fn = nullptr;
    if (!fn) {
        cudaDriverEntryPointQueryResult qr;
        cudaGetDriverEntryPointByVersion("cuTensorMapEncodeTiled", (void**)&fn, 12000,
                                         cudaEnableDefault, &qr);
    }
    return fn;
}
static void make_map(CUtensorMap* m, const __half* base, unsigned long long inner,
                     unsigned long long outer, unsigned box_in, unsigned box_out) {
    cuuint64_t dims[2] = { inner, outer };
    cuuint64_t strides[1] = { inner * 2 };
    cuuint32_t box[2] = { box_in, box_out };
    cuuint32_t es[2] = { 1, 1 };
    tmap_fn()(m, CU_TENSOR_MAP_DATA_TYPE_FLOAT16, 2, (void*)base, dims, strides, box, es,
              CU_TENSOR_MAP_INTERLEAVE_NONE, CU_TENSOR_MAP_SWIZZLE_128B,
              CU_TENSOR_MAP_L2_PROMOTION_L2_128B, CU_TENSOR_MAP_FLOAT_OOB_FILL_NONE);
}

// ========================= launch =========================
extern "C" void kernel_launch(void* const* d_in, const int* in_sizes, int n_in,
                              void* d_out, int out_size)
{
    const float* x   = (const float*)d_in[0];
    const int*   t   = (const int*)  d_in[1];
    const float* yv  = (const float*)d_in[2];
    const float* dv  = (const float*)d_in[3];
    const float* tw0 = (const float*)d_in[4];
    const float* tb0 = (const float*)d_in[5];
    const float* tw1 = (const float*)d_in[6];
    const float* tb1 = (const float*)d_in[7];
    const float* tw2 = (const float*)d_in[8];
    const float* tb2 = (const float*)d_in[9];
    const float* yw0 = (const float*)d_in[10];
    const float* yb0 = (const float*)d_in[11];
    const float* yw1 = (const float*)d_in[12];
    const float* yb1 = (const float*)d_in[13];
    const float* yhW = (const float*)d_in[14];
    const float* yhb = (const float*)d_in[15];
    const float* dw0 = (const float*)d_in[16];
    const float* db0 = (const float*)d_in[17];
    const float* dw1 = (const float*)d_in[18];
    const float* db1 = (const float*)d_in[19];
    const float* dhW = (const float*)d_in[20];
    const float* dhb = (const float*)d_in[21];
    const float* zw0 = (const float*)d_in[22];
    const float* zb0 = (const float*)d_in[23];
    const float* zw1 = (const float*)d_in[24];
    const float* zb1 = (const float*)d_in[25];
    const float* zhW = (const float*)d_in[26];
    const float* zhb = (const float*)d_in[27];
    float* out = (float*)d_out;

    __half *xh, *y1, *d1, *z1, *z2, *t1, *wh, *fy, *fd, *ft;
    int *posmap;
    cudaGetSymbolAddress((void**)&xh, g_x);
    cudaGetSymbolAddress((void**)&y1, g_y1);
    cudaGetSymbolAddress((void**)&d1, g_d1);
    cudaGetSymbolAddress((void**)&z1, g_z1);
    cudaGetSymbolAddress((void**)&z2, g_z2);
    cudaGetSymbolAddress((void**)&t1, g_t1);
    cudaGetSymbolAddress((void**)&wh, g_wh);
    cudaGetSymbolAddress((void**)&fy, g_fy);
    cudaGetSymbolAddress((void**)&fd, g_fd);
    cudaGetSymbolAddress((void**)&ft, g_ft);
    cudaGetSymbolAddress((void**)&posmap, g_pos);

    static cudaStream_t s1, s2, s3;
    static cudaEvent_t eL2, eJ1, eJ2, eJ3;
    static bool init = false;
    if (!init) {
        cudaStreamCreateWithFlags(&s1, cudaStreamNonBlocking);
        cudaStreamCreateWithFlags(&s2, cudaStreamNonBlocking);
        cudaStreamCreateWithFlags(&s3, cudaStreamNonBlocking);
        cudaEventCreateWithFlags(&eL2, cudaEventDisableTiming);
        cudaEventCreateWithFlags(&eJ1, cudaEventDisableTiming);
        cudaEventCreateWithFlags(&eJ2, cudaEventDisableTiming);
        cudaEventCreateWithFlags(&eJ3, cudaEventDisableTiming);
        cudaFuncSetAttribute((const void*)gemmL1, cudaFuncAttributeMaxDynamicSharedMemorySize, SMEM_REQ);
        cudaFuncSetAttribute((const void*)gemmL2, cudaFuncAttributeMaxDynamicSharedMemorySize, SMEM_REQ);
        cudaFuncSetAttribute((const void*)zheadT, cudaFuncAttributeMaxDynamicSharedMemorySize, SMEM_REQ);
        init = true;
    }

    static CUtensorMap M[12];
    make_map(&M[0],  xh, 1024, BATCH, 64, 256);
    make_map(&M[1],  y1, 1024, BATCH, 64, 256);
    make_map(&M[2],  d1, 1024, BATCH, 64, 256);
    make_map(&M[3],  z1, 1024, BATCH, 64, 256);
    make_map(&M[4],  z2, 1024, BATCH, 64, 256);
    make_map(&M[5],  t1, 256,  BATCH, 64, 256);
    make_map(&M[6],  wh + OFF_TW1, 256,  256,  64, 128);
    make_map(&M[7],  wh + OFF_L1,  1024, 3328, 64, 128);
    make_map(&M[8],  wh + OFF_YW1, 1024, 1024, 64, 128);
    make_map(&M[9],  wh + OFF_DW1, 1024, 1024, 64, 128);
    make_map(&M[10], wh + OFF_ZW1, 1024, 1024, 64, 128);
    make_map(&M[11], wh + OFF_ZHW, 1024, 3584, 64, 128);

    bucket_all<<<1, 1024>>>(t);
    xconv_kernel<<<(BATCH * 1024 / 2 + 255) / 256, 256>>>(x, xh, BATCH * 1024);
    WTab tab;
    tab.e[0]  = { tw1,            OFF_TW1,               256,  256 };
    tab.e[1]  = { yw0,            OFF_L1,                1024, 1024 };
    tab.e[2]  = { dw0,            OFF_L1 + 1048576ull,   1024, 1024 };
    tab.e[3]  = { zw0 + 2 * 1024, OFF_L1 + 2097152ull,   1024, 1024 };
    tab.e[4]  = { tw0,            OFF_L1 + 3145728ull,   1024, 256 };
    tab.e[5]  = { yw1,            OFF_YW1,               1024, 1024 };
    tab.e[6]  = { dw1,            OFF_DW1,               1024, 1024 };
    tab.e[7]  = { zw1,            OFF_ZW1,               1024, 1024 };
    for (int g = 0; g < 7; g++)
        tab.e[8 + g] = { zhW + (size_t)g * 1024 * 512,
                         (unsigned long long)(OFF_ZHW + (size_t)g * 524288), 1024, 512 };
    wconv_all<<<dim3(32, 32, 15), dim3(32, 8)>>>(tab, wh);

    // ---- L1 mega (y|d|z|t layer-1) ----
    L1Out O;
    O.o[0] = y1; O.bias[0] = yb0;
    O.o[1] = d1; O.bias[1] = db0;
    O.o[2] = z1; O.bias[2] = zb0;
    O.o[3] = t1; O.bias[3] = tb0;
    gemmL1<<<148, 512, SMEM_REQ>>>(M[0], M[7], O, yv, dv, zw0, posmap);

    // ---- L2 mega (y2 | d2 | z2 | t2) ----
    gemmL2<<<148, 512, SMEM_REQ>>>(M[1], M[2], M[3], M[5],
                                   M[8], M[9], M[10], M[6],
                                   yb1, db1, zb1, tb1, fy, fd, z2, ft);
    cudaEventRecord(eL2, 0);

    const int headBlocks = (BATCH * 32) / 256;

    // ---- tails on streams ----
    cudaStreamWaitEvent(s1, eL2, 0);
    thead_kernel<<<headBlocks, 256, 0, s1>>>(ft, tw2, tb2, out);
    cudaEventRecord(eJ1, s1);

    cudaStreamWaitEvent(s2, eL2, 0);
    head2_kernel<<<headBlocks, 256, 0, s2>>>(fy, t, yhW, yhb, out, 7);
    head2_kernel<<<headBlocks, 256, 0, s2>>>(fd, t, dhW, dhb, out, 9);
    cudaEventRecord(eJ2, s2);

    cudaStreamWaitEvent(s3, eL2, 0);
    zheadT<<<dim3(4, 64, 7), 512, SMEM_REQ, s3>>>(M[4], M[11], zhb, out);
    cudaEventRecord(eJ3, s3);

    cudaStreamWaitEvent(0, eJ1, 0);
    cudaStreamWaitEvent(0, eJ2, 0);
    cudaStreamWaitEvent(0, eJ3, 0);
}